// round 1
// baseline (speedup 1.0000x reference)
#include <cuda_runtime.h>
#include <cstdint>

#define B_  4
#define T_  1024
#define D_  512
#define C_  8
#define H_  8
#define HD_ 64
#define BT_ (B_*T_)
#define TD3_ (3*D_)

// ---------------- scratch (device globals; no allocation allowed) ----------------
__device__ int   g_assign[BT_];
__device__ int   g_counts[B_*C_];
__device__ int   g_idx[B_*C_*T_];
__device__ float g_qkv[(size_t)BT_*TD3_];   // [b*T+t, 3D]  (q | k | v), 25 MB
__device__ float g_O[(size_t)BT_*D_];       // attention output, 8 MB

// ---------------- 1) cluster argmax: one warp per token ----------------
__global__ void assign_kernel(const float* __restrict__ X,
                              const float* __restrict__ Wc,
                              const float* __restrict__ bc) {
    int gw   = (blockIdx.x * blockDim.x + threadIdx.x) >> 5;
    int lane = threadIdx.x & 31;
    if (gw >= BT_) return;
    const float* x = X + (size_t)gw * D_;
    float acc[C_];
#pragma unroll
    for (int c = 0; c < C_; c++) acc[c] = 0.f;
    for (int d = lane; d < D_; d += 32) {
        float xv = x[d];
#pragma unroll
        for (int c = 0; c < C_; c++) acc[c] += xv * Wc[c * D_ + d];
    }
#pragma unroll
    for (int c = 0; c < C_; c++)
#pragma unroll
        for (int o = 16; o; o >>= 1) acc[c] += __shfl_xor_sync(0xffffffffu, acc[c], o);
    if (lane == 0) {
        float best = acc[0] + bc[0];
        int bi = 0;
#pragma unroll
        for (int c = 1; c < C_; c++) {
            float v = acc[c] + bc[c];
            if (v > best) { best = v; bi = c; }   // ties -> first index, matches argmax
        }
        g_assign[gw] = bi;
    }
}

// ---------------- 2) deterministic per-(b,c) token lists ----------------
__global__ void build_lists_kernel() {
    int b = blockIdx.x / C_, c = blockIdx.x % C_;
    __shared__ int sc[256];
    __shared__ int s_base;
    int tid = threadIdx.x;
    if (tid == 0) s_base = 0;
    __syncthreads();
    int* out = g_idx + (b * C_ + c) * T_;
    for (int t0 = 0; t0 < T_; t0 += 256) {
        int t = t0 + tid;
        int p = (g_assign[b * T_ + t] == c) ? 1 : 0;
        sc[tid] = p;
        __syncthreads();
        for (int off = 1; off < 256; off <<= 1) {          // Hillis-Steele inclusive scan
            int add = (tid >= off) ? sc[tid - off] : 0;
            __syncthreads();
            sc[tid] += add;
            __syncthreads();
        }
        if (p) out[s_base + sc[tid] - 1] = t;
        __syncthreads();
        if (tid == 0) s_base += sc[255];
        __syncthreads();
    }
    if (tid == 0) g_counts[b * C_ + c] = s_base;
}

// ---------------- 3/5) fp32 NT GEMM: C[M,N] = A[M,K] * B[N,K]^T + bias[N] ----------------
// BM=BN=128, BK=8, 256 threads, 8x8 microtile. M%128==0, N%128==0, K%8==0.
__global__ __launch_bounds__(256) void gemm_nt_kernel(
    const float* __restrict__ A, const float* __restrict__ Bm,
    const float* __restrict__ bias, float* __restrict__ Cm,
    int M, int N, int K)
{
    __shared__ float As[8][128];
    __shared__ float Bs[8][128];
    const int tid = threadIdx.x;
    const int tx = tid & 15, ty = tid >> 4;
    const int m0 = blockIdx.y * 128, n0 = blockIdx.x * 128;
    const int lr = tid >> 1;            // 0..127
    const int lc = (tid & 1) * 4;       // 0 or 4
    const float* aPtr = A  + (size_t)(m0 + lr) * K + lc;
    const float* bPtr = Bm + (size_t)(n0 + lr) * K + lc;

    float acc[8][8];
#pragma unroll
    for (int i = 0; i < 8; i++)
#pragma unroll
        for (int j = 0; j < 8; j++) acc[i][j] = 0.f;

    for (int k0 = 0; k0 < K; k0 += 8) {
        float4 av = *(const float4*)(aPtr + k0);
        float4 bv = *(const float4*)(bPtr + k0);
        As[lc + 0][lr] = av.x; As[lc + 1][lr] = av.y;
        As[lc + 2][lr] = av.z; As[lc + 3][lr] = av.w;
        Bs[lc + 0][lr] = bv.x; Bs[lc + 1][lr] = bv.y;
        Bs[lc + 2][lr] = bv.z; Bs[lc + 3][lr] = bv.w;
        __syncthreads();
#pragma unroll
        for (int k = 0; k < 8; k++) {
            float a[8], bb[8];
            *(float4*)(a)      = *(const float4*)&As[k][ty * 8];
            *(float4*)(a + 4)  = *(const float4*)&As[k][ty * 8 + 4];
            *(float4*)(bb)     = *(const float4*)&Bs[k][tx * 8];
            *(float4*)(bb + 4) = *(const float4*)&Bs[k][tx * 8 + 4];
#pragma unroll
            for (int i = 0; i < 8; i++)
#pragma unroll
                for (int j = 0; j < 8; j++)
                    acc[i][j] = fmaf(a[i], bb[j], acc[i][j]);
        }
        __syncthreads();
    }
#pragma unroll
    for (int i = 0; i < 8; i++) {
        float* cp = Cm + (size_t)(m0 + ty * 8 + i) * N + n0 + tx * 8;
#pragma unroll
        for (int j = 0; j < 8; j++)
            cp[j] = acc[i][j] + bias[n0 + tx * 8 + j];
    }
}

// ---------------- 4) clustered attention with phantom (masked-token) key ----------------
// block per (b, c, h); 8 warps; warp-per-query; online softmax over gathered keys.
__global__ __launch_bounds__(256) void attn_kernel(const float* __restrict__ bin) {
    int bid = blockIdx.x;
    int h = bid % H_;
    int c = (bid / H_) % C_;
    int b = bid / (H_ * C_);
    int n = g_counts[b * C_ + c];
    if (n == 0) return;
    const int* idx = g_idx + (b * C_ + c) * T_;

    __shared__ int   s_idx[T_];       // 4 KB
    __shared__ float Ksh[64][64];     // [d][j], 16 KB
    __shared__ float Vsh[64][64];     // [j][d], 16 KB
    __shared__ float Qsh[8][64];      // 2 KB (pre-scaled by 1/sqrt(hd))
    __shared__ float Psh[8][64];      // 2 KB

    const int tid = threadIdx.x, lane = tid & 31, wid = tid >> 5;
    for (int i = tid; i < n; i += 256) s_idx[i] = idx[i];
    __syncthreads();

    const float w0 = (float)(T_ - n);           // phantom-key multiplicity
    const float* bk = bin + D_     + h * HD_;   // k-bias slice (head h)
    const float* bv = bin + 2 * D_ + h * HD_;   // v-bias slice
    const float scale = 0.125f;                 // 1/sqrt(64)

    const int nq = (n + 7) / 8;
    for (int qc = 0; qc < nq; qc++) {
        int qi = qc * 8 + wid;
        bool active = qi < n;
        int tq = active ? s_idx[qi] : s_idx[0];
        const float* qptr = g_qkv + (size_t)(b * T_ + tq) * TD3_ + h * HD_;
        Qsh[wid][lane]      = qptr[lane]      * scale;
        Qsh[wid][lane + 32] = qptr[lane + 32] * scale;
        __syncwarp();

        // phantom init: m = q~.bk, l = w0, acc = w0 * bv
        float s0 = Qsh[wid][lane] * bk[lane] + Qsh[wid][lane + 32] * bk[lane + 32];
#pragma unroll
        for (int o = 16; o; o >>= 1) s0 += __shfl_xor_sync(0xffffffffu, s0, o);
        float m = s0, l = w0;
        float acc0 = w0 * bv[lane], acc1 = w0 * bv[lane + 32];

        for (int kt = 0; kt < n; kt += 64) {
            int nt = min(64, n - kt);
            __syncthreads();
            {   // cooperative gather of K (transposed) and V tiles
                int j = tid >> 2;                // 0..63
                int dp = (tid & 3) * 16;
                if (j < nt) {
                    int tk = s_idx[kt + j];
                    const float* kp = g_qkv + (size_t)(b * T_ + tk) * TD3_ + D_     + h * HD_ + dp;
                    const float* vp = g_qkv + (size_t)(b * T_ + tk) * TD3_ + 2 * D_ + h * HD_ + dp;
#pragma unroll
                    for (int q4 = 0; q4 < 4; q4++) {
                        float4 kv = ((const float4*)kp)[q4];
                        Ksh[dp + q4 * 4 + 0][j] = kv.x;
                        Ksh[dp + q4 * 4 + 1][j] = kv.y;
                        Ksh[dp + q4 * 4 + 2][j] = kv.z;
                        Ksh[dp + q4 * 4 + 3][j] = kv.w;
                        ((float4*)&Vsh[j][dp])[q4] = ((const float4*)vp)[q4];
                    }
                }
            }
            __syncthreads();

            // scores for keys jA=lane, jB=lane+32
            float sA = -1e30f, sB = -1e30f;
            if (lane < nt) {
                float s = 0.f;
#pragma unroll
                for (int d = 0; d < 64; d++) s += Qsh[wid][d] * Ksh[d][lane];
                sA = s;
            }
            if (lane + 32 < nt) {
                float s = 0.f;
#pragma unroll
                for (int d = 0; d < 64; d++) s += Qsh[wid][d] * Ksh[d][lane + 32];
                sB = s;
            }
            float mt = fmaxf(sA, sB);
#pragma unroll
            for (int o = 16; o; o >>= 1) mt = fmaxf(mt, __shfl_xor_sync(0xffffffffu, mt, o));
            float mnew = fmaxf(m, mt);
            float corr = __expf(m - mnew);
            float p0 = (lane      < nt) ? __expf(sA - mnew) : 0.f;
            float p1 = (lane + 32 < nt) ? __expf(sB - mnew) : 0.f;
            float ps = p0 + p1;
#pragma unroll
            for (int o = 16; o; o >>= 1) ps += __shfl_xor_sync(0xffffffffu, ps, o);
            l = l * corr + ps;
            acc0 *= corr; acc1 *= corr;
            m = mnew;
            Psh[wid][lane] = p0; Psh[wid][lane + 32] = p1;
            __syncwarp();
            for (int j = 0; j < nt; j++) {
                float p = Psh[wid][j];
                acc0 = fmaf(p, Vsh[j][lane],      acc0);
                acc1 = fmaf(p, Vsh[j][lane + 32], acc1);
            }
        }

        if (active) {
            float invl = 1.0f / l;
            float* op = g_O + (size_t)(b * T_ + tq) * D_ + h * HD_;
            op[lane]      = acc0 * invl;
            op[lane + 32] = acc1 * invl;
        }
    }
}

// ---------------- launcher ----------------
extern "C" void kernel_launch(void* const* d_in, const int* in_sizes, int n_in,
                              void* d_out, int out_size) {
    const float* X    = (const float*)d_in[0];
    const float* Wc   = (const float*)d_in[1];
    const float* bc   = (const float*)d_in[2];
    const float* Win  = (const float*)d_in[3];
    const float* bin  = (const float*)d_in[4];
    const float* Wout = (const float*)d_in[5];
    const float* bout = (const float*)d_in[6];
    float* out = (float*)d_out;

    void* qkv_p = nullptr; cudaGetSymbolAddress(&qkv_p, g_qkv);
    void* O_p   = nullptr; cudaGetSymbolAddress(&O_p, g_O);

    assign_kernel<<<BT_ / 8, 256>>>(X, Wc, bc);
    build_lists_kernel<<<B_ * C_, 256>>>();
    gemm_nt_kernel<<<dim3(TD3_ / 128, BT_ / 128), 256>>>(X, Win, bin, (float*)qkv_p,
                                                         BT_, TD3_, D_);
    attn_kernel<<<B_ * C_ * H_, 256>>>(bin);
    gemm_nt_kernel<<<dim3(D_ / 128, BT_ / 128), 256>>>((const float*)O_p, Wout, bout, out,
                                                       BT_, D_, D_);
}

// round 2
// speedup vs baseline: 1.4177x; 1.4177x over previous
#include <cuda_runtime.h>
#include <cstdint>

#define B_  4
#define T_  1024
#define D_  512
#define C_  8
#define H_  8
#define HD_ 64
#define BT_ (B_*T_)
#define TD3_ (3*D_)

// ---------------- scratch (device globals; no allocation allowed) ----------------
__device__ int   g_assign[BT_];
__device__ int   g_counts[B_*C_];
__device__ int   g_idx[B_*C_*T_];
__device__ float g_qkv[(size_t)BT_*TD3_];   // [b*T+t, 3D]  (q | k | v)
__device__ float g_O[(size_t)BT_*D_];       // attention output

// ---------------- 1) cluster argmax: one warp per token ----------------
__global__ void assign_kernel(const float* __restrict__ X,
                              const float* __restrict__ Wc,
                              const float* __restrict__ bc) {
    int gw   = (blockIdx.x * blockDim.x + threadIdx.x) >> 5;
    int lane = threadIdx.x & 31;
    if (gw >= BT_) return;
    const float* x = X + (size_t)gw * D_;
    float acc[C_];
#pragma unroll
    for (int c = 0; c < C_; c++) acc[c] = 0.f;
    for (int d = lane; d < D_; d += 32) {
        float xv = x[d];
#pragma unroll
        for (int c = 0; c < C_; c++) acc[c] += xv * Wc[c * D_ + d];
    }
#pragma unroll
    for (int c = 0; c < C_; c++)
#pragma unroll
        for (int o = 16; o; o >>= 1) acc[c] += __shfl_xor_sync(0xffffffffu, acc[c], o);
    if (lane == 0) {
        float best = acc[0] + bc[0];
        int bi = 0;
#pragma unroll
        for (int c = 1; c < C_; c++) {
            float v = acc[c] + bc[c];
            if (v > best) { best = v; bi = c; }
        }
        g_assign[gw] = bi;
    }
}

// ---------------- 2) deterministic per-(b,c) token lists ----------------
__global__ void build_lists_kernel() {
    int b = blockIdx.x / C_, c = blockIdx.x % C_;
    __shared__ int sc[256];
    __shared__ int s_base;
    int tid = threadIdx.x;
    if (tid == 0) s_base = 0;
    __syncthreads();
    int* out = g_idx + (b * C_ + c) * T_;
    for (int t0 = 0; t0 < T_; t0 += 256) {
        int t = t0 + tid;
        int p = (g_assign[b * T_ + t] == c) ? 1 : 0;
        sc[tid] = p;
        __syncthreads();
        for (int off = 1; off < 256; off <<= 1) {
            int add = (tid >= off) ? sc[tid - off] : 0;
            __syncthreads();
            sc[tid] += add;
            __syncthreads();
        }
        if (p) out[s_base + sc[tid] - 1] = t;
        __syncthreads();
        if (tid == 0) s_base += sc[255];
        __syncthreads();
    }
    if (tid == 0) g_counts[b * C_ + c] = s_base;
}

// ---------------- 3/5) fp32 NT GEMM, double-buffered ----------------
// C[M,N] = A[M,K] * B[N,K]^T + bias[N]; BM=BN=128, BK=8, 256 thr, 8x8 microtile.
__global__ __launch_bounds__(256) void gemm_nt_kernel(
    const float* __restrict__ A, const float* __restrict__ Bm,
    const float* __restrict__ bias, float* __restrict__ Cm,
    int M, int N, int K)
{
    __shared__ float As[2][8][128];
    __shared__ float Bs[2][8][128];
    const int tid = threadIdx.x;
    const int tx = tid & 15, ty = tid >> 4;
    const int m0 = blockIdx.y * 128, n0 = blockIdx.x * 128;
    const int lr = tid >> 1;            // 0..127
    const int lc = (tid & 1) * 4;       // 0 or 4
    const float* aPtr = A  + (size_t)(m0 + lr) * K + lc;
    const float* bPtr = Bm + (size_t)(n0 + lr) * K + lc;

    float acc[8][8];
#pragma unroll
    for (int i = 0; i < 8; i++)
#pragma unroll
        for (int j = 0; j < 8; j++) acc[i][j] = 0.f;

    float4 av = *(const float4*)(aPtr);
    float4 bv = *(const float4*)(bPtr);
    As[0][lc + 0][lr] = av.x; As[0][lc + 1][lr] = av.y;
    As[0][lc + 2][lr] = av.z; As[0][lc + 3][lr] = av.w;
    Bs[0][lc + 0][lr] = bv.x; Bs[0][lc + 1][lr] = bv.y;
    Bs[0][lc + 2][lr] = bv.z; Bs[0][lc + 3][lr] = bv.w;
    __syncthreads();

    int buf = 0;
    for (int k0 = 8; k0 < K; k0 += 8) {
        av = *(const float4*)(aPtr + k0);
        bv = *(const float4*)(bPtr + k0);
#pragma unroll
        for (int k = 0; k < 8; k++) {
            float a[8], bb[8];
            *(float4*)(a)      = *(const float4*)&As[buf][k][ty * 8];
            *(float4*)(a + 4)  = *(const float4*)&As[buf][k][ty * 8 + 4];
            *(float4*)(bb)     = *(const float4*)&Bs[buf][k][tx * 8];
            *(float4*)(bb + 4) = *(const float4*)&Bs[buf][k][tx * 8 + 4];
#pragma unroll
            for (int i = 0; i < 8; i++)
#pragma unroll
                for (int j = 0; j < 8; j++)
                    acc[i][j] = fmaf(a[i], bb[j], acc[i][j]);
        }
        int nb = buf ^ 1;
        As[nb][lc + 0][lr] = av.x; As[nb][lc + 1][lr] = av.y;
        As[nb][lc + 2][lr] = av.z; As[nb][lc + 3][lr] = av.w;
        Bs[nb][lc + 0][lr] = bv.x; Bs[nb][lc + 1][lr] = bv.y;
        Bs[nb][lc + 2][lr] = bv.z; Bs[nb][lc + 3][lr] = bv.w;
        __syncthreads();
        buf = nb;
    }
#pragma unroll
    for (int k = 0; k < 8; k++) {
        float a[8], bb[8];
        *(float4*)(a)      = *(const float4*)&As[buf][k][ty * 8];
        *(float4*)(a + 4)  = *(const float4*)&As[buf][k][ty * 8 + 4];
        *(float4*)(bb)     = *(const float4*)&Bs[buf][k][tx * 8];
        *(float4*)(bb + 4) = *(const float4*)&Bs[buf][k][tx * 8 + 4];
#pragma unroll
        for (int i = 0; i < 8; i++)
#pragma unroll
            for (int j = 0; j < 8; j++)
                acc[i][j] = fmaf(a[i], bb[j], acc[i][j]);
    }
#pragma unroll
    for (int i = 0; i < 8; i++) {
        float* cp = Cm + (size_t)(m0 + ty * 8 + i) * N + n0 + tx * 8;
#pragma unroll
        for (int j = 0; j < 8; j++)
            cp[j] = acc[i][j] + bias[n0 + tx * 8 + j];
    }
}

// ---------------- 4) flash-style clustered attention with phantom key ----------------
// block per (b,c,h); 64-query tiles, 64-key tiles; 4x4 register microtiles.
// smem words: s_idx 1024(int) | Qs 64x64 (d-major) | Ks 64x64 (d-major)
//             | Vs 64x68 (k-major, padded) | Ps 64x64 (q-major) | ph4 256 | ph 64
#define ATTN_SMEM ((1024 + 4096 + 4096 + 64*68 + 4096 + 256 + 64) * 4)

__global__ __launch_bounds__(256) void attn_kernel(const float* __restrict__ bin) {
    extern __shared__ float smf[];
    int*   s_idx = (int*)smf;
    float* Qs  = smf + 1024;
    float* Ks  = Qs + 4096;
    float* Vs  = Ks + 4096;
    float* Ps  = Vs + 64 * 68;
    float* ph4 = Ps + 4096;
    float* ph  = ph4 + 256;

    const int bid = blockIdx.x;
    const int h = bid & 7;
    const int c = (bid >> 3) & 7;
    const int b = bid >> 6;
    const int n = g_counts[b * C_ + c];
    if (n == 0) return;
    const int* idx = g_idx + (b * C_ + c) * T_;
    const int tid = threadIdx.x;
    for (int i = tid; i < n; i += 256) s_idx[i] = idx[i];
    __syncthreads();

    const float w0 = (float)(T_ - n);
    const float* bk = bin + D_     + h * HD_;
    const float* bv = bin + 2 * D_ + h * HD_;
    const int tx = tid & 15, ty = tid >> 4;
    const int gq = tid & 63, gd = tid >> 6;          // Q/K gather map
    const int vj = tid >> 2, vdp = (tid & 3) * 16;   // V gather map

    float bvj[4];
#pragma unroll
    for (int j = 0; j < 4; j++) bvj[j] = bv[tx * 4 + j];

    for (int qt = 0; qt < n; qt += 64) {
        const int nq = min(64, n - qt);
        // gather Q (pre-scaled) + phantom-score partials
        {
            float p = 0.f;
            if (gq < nq) {
                const float* qp = g_qkv + (size_t)(b * T_ + s_idx[qt + gq]) * TD3_ + h * HD_ + gd * 16;
#pragma unroll
                for (int i = 0; i < 16; i++) {
                    float v = qp[i] * 0.125f;
                    Qs[(gd * 16 + i) * 64 + gq] = v;
                    p = fmaf(v, bk[gd * 16 + i], p);
                }
            } else {
#pragma unroll
                for (int i = 0; i < 16; i++) Qs[(gd * 16 + i) * 64 + gq] = 0.f;
            }
            ph4[gq * 4 + gd] = p;
        }
        __syncthreads();
        if (tid < 64)
            ph[tid] = (ph4[tid * 4] + ph4[tid * 4 + 1]) + (ph4[tid * 4 + 2] + ph4[tid * 4 + 3]);
        __syncthreads();

        float m[4], l[4], acc[4][4];
#pragma unroll
        for (int i = 0; i < 4; i++) {
            m[i] = ph[ty * 4 + i];
            l[i] = w0;
#pragma unroll
            for (int j = 0; j < 4; j++) acc[i][j] = w0 * bvj[j];
        }

        for (int kt = 0; kt < n; kt += 64) {
            const int nk = min(64, n - kt);
            __syncthreads();                         // prev tile's PV reads done
            // gather K (transposed, zero-padded)
            if (gq < nk) {
                const float* kp = g_qkv + (size_t)(b * T_ + s_idx[kt + gq]) * TD3_ + D_ + h * HD_ + gd * 16;
#pragma unroll
                for (int i = 0; i < 16; i++) Ks[(gd * 16 + i) * 64 + gq] = kp[i];
            } else {
#pragma unroll
                for (int i = 0; i < 16; i++) Ks[(gd * 16 + i) * 64 + gq] = 0.f;
            }
            // gather V (row-major, zero-padded)
            if (vj < nk) {
                const float* vp = g_qkv + (size_t)(b * T_ + s_idx[kt + vj]) * TD3_ + 2 * D_ + h * HD_ + vdp;
#pragma unroll
                for (int q4 = 0; q4 < 4; q4++)
                    *(float4*)&Vs[vj * 68 + vdp + q4 * 4] = ((const float4*)vp)[q4];
            } else {
#pragma unroll
                for (int q4 = 0; q4 < 4; q4++)
                    *(float4*)&Vs[vj * 68 + vdp + q4 * 4] = make_float4(0.f, 0.f, 0.f, 0.f);
            }
            __syncthreads();

            // S = Q·K^T, 4x4 per thread
            float S[4][4];
#pragma unroll
            for (int i = 0; i < 4; i++)
#pragma unroll
                for (int j = 0; j < 4; j++) S[i][j] = 0.f;
#pragma unroll 8
            for (int d = 0; d < 64; d++) {
                float4 aq = *(const float4*)&Qs[d * 64 + ty * 4];
                float4 kk = *(const float4*)&Ks[d * 64 + tx * 4];
                float a[4] = {aq.x, aq.y, aq.z, aq.w};
                float kb[4] = {kk.x, kk.y, kk.z, kk.w};
#pragma unroll
                for (int i = 0; i < 4; i++)
#pragma unroll
                    for (int j = 0; j < 4; j++)
                        S[i][j] = fmaf(a[i], kb[j], S[i][j]);
            }

            // online softmax update per row + write P (row-major, conflict-free)
#pragma unroll
            for (int i = 0; i < 4; i++) {
                float mt = -3.0e38f;
#pragma unroll
                for (int j = 0; j < 4; j++)
                    if (tx * 4 + j < nk) mt = fmaxf(mt, S[i][j]);
#pragma unroll
                for (int o = 8; o; o >>= 1) mt = fmaxf(mt, __shfl_xor_sync(0xffffffffu, mt, o));
                float mnew = fmaxf(m[i], mt);
                float corr = __expf(m[i] - mnew);
                float ps = 0.f;
#pragma unroll
                for (int j = 0; j < 4; j++) {
                    float p = (tx * 4 + j < nk) ? __expf(S[i][j] - mnew) : 0.f;
                    S[i][j] = p; ps += p;
                }
#pragma unroll
                for (int o = 8; o; o >>= 1) ps += __shfl_xor_sync(0xffffffffu, ps, o);
                l[i] = l[i] * corr + ps;
                m[i] = mnew;
#pragma unroll
                for (int j = 0; j < 4; j++) acc[i][j] *= corr;
                *(float4*)&Ps[(ty * 4 + i) * 64 + tx * 4] =
                    make_float4(S[i][0], S[i][1], S[i][2], S[i][3]);
            }
            __syncthreads();

            // O += P·V (broadcast P reads + float4 V reads)
#pragma unroll 4
            for (int k2 = 0; k2 < 64; k2++) {
                float4 vv = *(const float4*)&Vs[k2 * 68 + tx * 4];
#pragma unroll
                for (int i = 0; i < 4; i++) {
                    float p = Ps[(ty * 4 + i) * 64 + k2];
                    acc[i][0] = fmaf(p, vv.x, acc[i][0]);
                    acc[i][1] = fmaf(p, vv.y, acc[i][1]);
                    acc[i][2] = fmaf(p, vv.z, acc[i][2]);
                    acc[i][3] = fmaf(p, vv.w, acc[i][3]);
                }
            }
        }

        // epilogue: normalize + scatter store
#pragma unroll
        for (int i = 0; i < 4; i++) {
            int qi = qt + ty * 4 + i;
            if (qi < n) {
                float invl = 1.0f / l[i];
                float* op = g_O + (size_t)(b * T_ + s_idx[qi]) * D_ + h * HD_ + tx * 4;
#pragma unroll
                for (int j = 0; j < 4; j++) op[j] = acc[i][j] * invl;
            }
        }
    }
}

// ---------------- launcher ----------------
extern "C" void kernel_launch(void* const* d_in, const int* in_sizes, int n_in,
                              void* d_out, int out_size) {
    const float* X    = (const float*)d_in[0];
    const float* Wc   = (const float*)d_in[1];
    const float* bc   = (const float*)d_in[2];
    const float* Win  = (const float*)d_in[3];
    const float* bin  = (const float*)d_in[4];
    const float* Wout = (const float*)d_in[5];
    const float* bout = (const float*)d_in[6];
    float* out = (float*)d_out;

    void* qkv_p = nullptr; cudaGetSymbolAddress(&qkv_p, g_qkv);
    void* O_p   = nullptr; cudaGetSymbolAddress(&O_p, g_O);

    cudaFuncSetAttribute(attn_kernel, cudaFuncAttributeMaxDynamicSharedMemorySize, ATTN_SMEM);

    assign_kernel<<<BT_ / 8, 256>>>(X, Wc, bc);
    build_lists_kernel<<<B_ * C_, 256>>>();
    gemm_nt_kernel<<<dim3(TD3_ / 128, BT_ / 128), 256>>>(X, Win, bin, (float*)qkv_p,
                                                         BT_, TD3_, D_);
    attn_kernel<<<B_ * C_ * H_, 256, ATTN_SMEM>>>(bin);
    gemm_nt_kernel<<<dim3(D_ / 128, BT_ / 128), 256>>>((const float*)O_p, Wout, bout, out,
                                                       BT_, D_, D_);
}

// round 4
// speedup vs baseline: 2.2372x; 1.5780x over previous
#include <cuda_runtime.h>
#include <cstdint>

#define B_  4
#define T_  1024
#define D_  512
#define C_  8
#define H_  8
#define HD_ 64
#define BT_ (B_*T_)
#define TD3_ (3*D_)

// ---------------- scratch (device globals; no allocation allowed) ----------------
__device__ int   g_assign[BT_];
__device__ int   g_counts[B_*C_];
__device__ int   g_idx[B_*C_*T_];
__device__ float g_qkv[(size_t)BT_*TD3_];   // [b*T+t, 3D]  (q | k | v)
__device__ float g_O[(size_t)BT_*D_];       // attention output

// ---------------- 1) cluster argmax: one warp per token (exact fp32) ----------------
__global__ void assign_kernel(const float* __restrict__ X,
                              const float* __restrict__ Wc,
                              const float* __restrict__ bc) {
    int gw   = (blockIdx.x * blockDim.x + threadIdx.x) >> 5;
    int lane = threadIdx.x & 31;
    if (gw >= BT_) return;
    const float* x = X + (size_t)gw * D_;
    float acc[C_];
#pragma unroll
    for (int c = 0; c < C_; c++) acc[c] = 0.f;
    for (int d = lane; d < D_; d += 32) {
        float xv = x[d];
#pragma unroll
        for (int c = 0; c < C_; c++) acc[c] += xv * Wc[c * D_ + d];
    }
#pragma unroll
    for (int c = 0; c < C_; c++)
#pragma unroll
        for (int o = 16; o; o >>= 1) acc[c] += __shfl_xor_sync(0xffffffffu, acc[c], o);
    if (lane == 0) {
        float best = acc[0] + bc[0];
        int bi = 0;
#pragma unroll
        for (int c = 1; c < C_; c++) {
            float v = acc[c] + bc[c];
            if (v > best) { best = v; bi = c; }
        }
        g_assign[gw] = bi;
    }
}

// ---------------- 2) deterministic per-(b,c) token lists ----------------
__global__ void build_lists_kernel() {
    int b = blockIdx.x / C_, c = blockIdx.x % C_;
    __shared__ int sc[256];
    __shared__ int s_base;
    int tid = threadIdx.x;
    if (tid == 0) s_base = 0;
    __syncthreads();
    int* out = g_idx + (b * C_ + c) * T_;
    for (int t0 = 0; t0 < T_; t0 += 256) {
        int t = t0 + tid;
        int p = (g_assign[b * T_ + t] == c) ? 1 : 0;
        sc[tid] = p;
        __syncthreads();
        for (int off = 1; off < 256; off <<= 1) {
            int add = (tid >= off) ? sc[tid - off] : 0;
            __syncthreads();
            sc[tid] += add;
            __syncthreads();
        }
        if (p) out[s_base + sc[tid] - 1] = t;
        __syncthreads();
        if (tid == 0) s_base += sc[255];
        __syncthreads();
    }
    if (tid == 0) g_counts[b * C_ + c] = s_base;
}

// ---------------- 3/5) 3xTF32 mma.sync NT GEMM ----------------
// C[M,N] = A[M,K]*B[N,K]^T + bias[N]. BM=BN=128, BK=32, 256 thr (8 warps 2Mx4N),
// warp tile 64x32 = 4x4 m16n8k8. Double-buffered hi/lo SMEM planes, stride 33.
#define PADg  33
#define PLANE (128 * PADg)               // floats per plane
#define STAGEf (4 * PLANE)               // Ah | Al | Bh | Bl
#define GEMM_SMEM (2 * STAGEf * 4)       // bytes (135168)

__device__ __forceinline__ uint32_t tf32r(float x) {
    uint32_t u; asm("cvt.rna.tf32.f32 %0, %1;" : "=r"(u) : "f"(x));
    return u;
}
__device__ __forceinline__ void split1(float x, uint32_t& h, uint32_t& l) {
    h = tf32r(x);
    l = tf32r(x - __uint_as_float(h));
}
#define MMA_TF32(d, a, b) \
    asm volatile("mma.sync.aligned.m16n8k8.row.col.f32.tf32.tf32.f32 " \
                 "{%0,%1,%2,%3},{%4,%5,%6,%7},{%8,%9},{%0,%1,%2,%3};" \
                 : "+f"((d)[0]), "+f"((d)[1]), "+f"((d)[2]), "+f"((d)[3]) \
                 : "r"((a)[0]), "r"((a)[1]), "r"((a)[2]), "r"((a)[3]), \
                   "r"((b)[0]), "r"((b)[1]))

__global__ __launch_bounds__(256) void gemm_mma(const float* __restrict__ A,
                                                const float* __restrict__ Bm,
                                                const float* __restrict__ bias,
                                                float* __restrict__ Cm,
                                                int M, int N, int K) {
    extern __shared__ float sm[];
    const int tid = threadIdx.x, lane = tid & 31, w = tid >> 5;
    const int wm = w & 1, wn = w >> 1;
    const int qr = lane >> 2, qc = lane & 3;
    const int m0 = blockIdx.y * 128, n0 = blockIdx.x * 128;

    // LDG map: row lr (0..127), 16 consecutive k starting at lk
    const int lr = tid >> 1, lk = (tid & 1) * 16;
    const float* Ap = A  + (size_t)(m0 + lr) * K + lk;
    const float* Bp = Bm + (size_t)(n0 + lr) * K + lk;

    float acc[4][4][4];
#pragma unroll
    for (int i = 0; i < 4; i++)
#pragma unroll
        for (int j = 0; j < 4; j++)
#pragma unroll
            for (int e = 0; e < 4; e++) acc[i][j][e] = 0.f;

    float4 ra[4], rb[4];
    auto ldg = [&](int k0) {
#pragma unroll
        for (int i = 0; i < 4; i++) {
            ra[i] = *(const float4*)(Ap + k0 + 4 * i);
            rb[i] = *(const float4*)(Bp + k0 + 4 * i);
        }
    };
    auto sts = [&](int s) {
        float* Ah = sm + s * STAGEf;
        float* Al = Ah + PLANE;
        float* Bh = Al + PLANE;
        float* Bl = Bh + PLANE;
        const int base = lr * PADg + lk;
#pragma unroll
        for (int i = 0; i < 4; i++) {
            float v[4] = {ra[i].x, ra[i].y, ra[i].z, ra[i].w};
            float u[4] = {rb[i].x, rb[i].y, rb[i].z, rb[i].w};
#pragma unroll
            for (int e = 0; e < 4; e++) {
                uint32_t h, l;
                split1(v[e], h, l);
                ((uint32_t*)Ah)[base + 4 * i + e] = h;
                ((uint32_t*)Al)[base + 4 * i + e] = l;
                split1(u[e], h, l);
                ((uint32_t*)Bh)[base + 4 * i + e] = h;
                ((uint32_t*)Bl)[base + 4 * i + e] = l;
            }
        }
    };
    auto compute = [&](int s) {
        const uint32_t* Ah = (const uint32_t*)(sm + s * STAGEf);
        const uint32_t* Al = Ah + PLANE;
        const uint32_t* Bh = Al + PLANE;
        const uint32_t* Bl = Bh + PLANE;
#pragma unroll
        for (int ks = 0; ks < 4; ks++) {
            const int kk = ks * 8;
            uint32_t ah[4][4], al[4][4], bh[4][2], bl[4][2];
#pragma unroll
            for (int mt = 0; mt < 4; mt++) {
                int row = wm * 64 + mt * 16;
                int i0 = (row + qr) * PADg + kk + qc;
                int i1 = (row + qr + 8) * PADg + kk + qc;
                ah[mt][0] = Ah[i0];     ah[mt][1] = Ah[i1];
                ah[mt][2] = Ah[i0 + 4]; ah[mt][3] = Ah[i1 + 4];
                al[mt][0] = Al[i0];     al[mt][1] = Al[i1];
                al[mt][2] = Al[i0 + 4]; al[mt][3] = Al[i1 + 4];
            }
#pragma unroll
            for (int nt = 0; nt < 4; nt++) {
                int col = wn * 32 + nt * 8;
                int i0 = (col + qr) * PADg + kk + qc;
                bh[nt][0] = Bh[i0]; bh[nt][1] = Bh[i0 + 4];
                bl[nt][0] = Bl[i0]; bl[nt][1] = Bl[i0 + 4];
            }
#pragma unroll
            for (int mt = 0; mt < 4; mt++)
#pragma unroll
                for (int nt = 0; nt < 4; nt++) {
                    MMA_TF32(acc[mt][nt], ah[mt], bh[nt]);
                    MMA_TF32(acc[mt][nt], ah[mt], bl[nt]);
                    MMA_TF32(acc[mt][nt], al[mt], bh[nt]);
                }
        }
    };

    const int nch = K >> 5;
    ldg(0);
    sts(0);
    __syncthreads();
    for (int ch = 0; ch < nch; ch++) {
        int s = ch & 1;
        if (ch + 1 < nch) ldg((ch + 1) * 32);
        compute(s);
        if (ch + 1 < nch) sts(s ^ 1);
        __syncthreads();
    }

    // epilogue: frag rows m0+..+qr(+8), cols 2*qc(+1); float2 stores + bias
#pragma unroll
    for (int mt = 0; mt < 4; mt++) {
        int r = m0 + wm * 64 + mt * 16 + qr;
#pragma unroll
        for (int nt = 0; nt < 4; nt++) {
            int cc = n0 + wn * 32 + nt * 8 + 2 * qc;
            float b0 = bias[cc], b1 = bias[cc + 1];
            *(float2*)(Cm + (size_t)r * N + cc) =
                make_float2(acc[mt][nt][0] + b0, acc[mt][nt][1] + b1);
            *(float2*)(Cm + (size_t)(r + 8) * N + cc) =
                make_float2(acc[mt][nt][2] + b0, acc[mt][nt][3] + b1);
        }
    }
}

// ---------------- 4) flash-style clustered attention with phantom key ----------------
// grid = (b*c*h, qtile); block does one 64-query tile over all key tiles.
#define ATTN_SMEM ((1024 + 4096 + 4096 + 64*68 + 4096 + 256 + 64) * 4)

__global__ __launch_bounds__(256) void attn_kernel(const float* __restrict__ bin) {
    extern __shared__ float smf[];
    int*   s_idx = (int*)smf;
    float* Qs  = smf + 1024;
    float* Ks  = Qs + 4096;
    float* Vs  = Ks + 4096;
    float* Ps  = Vs + 64 * 68;
    float* ph4 = Ps + 4096;
    float* ph  = ph4 + 256;

    const int bid = blockIdx.x;
    const int h = bid & 7;
    const int c = (bid >> 3) & 7;
    const int b = bid >> 6;
    const int n = g_counts[b * C_ + c];
    const int qt = blockIdx.y * 64;
    if (qt >= n) return;
    const int* idx = g_idx + (b * C_ + c) * T_;
    const int tid = threadIdx.x;
    for (int i = tid; i < n; i += 256) s_idx[i] = idx[i];
    __syncthreads();

    const float w0 = (float)(T_ - n);
    const float* bk = bin + D_     + h * HD_;
    const float* bv = bin + 2 * D_ + h * HD_;
    const int tx = tid & 15, ty = tid >> 4;
    const int gq = tid & 63, gd = tid >> 6;
    const int vj = tid >> 2, vdp = (tid & 3) * 16;

    float bvj[4];
#pragma unroll
    for (int j = 0; j < 4; j++) bvj[j] = bv[tx * 4 + j];

    const int nq = min(64, n - qt);
    {
        float p = 0.f;
        if (gq < nq) {
            const float* qp = g_qkv + (size_t)(b * T_ + s_idx[qt + gq]) * TD3_ + h * HD_ + gd * 16;
#pragma unroll
            for (int i = 0; i < 16; i++) {
                float v = qp[i] * 0.125f;
                Qs[(gd * 16 + i) * 64 + gq] = v;
                p = fmaf(v, bk[gd * 16 + i], p);
            }
        } else {
#pragma unroll
            for (int i = 0; i < 16; i++) Qs[(gd * 16 + i) * 64 + gq] = 0.f;
        }
        ph4[gq * 4 + gd] = p;
    }
    __syncthreads();
    if (tid < 64)
        ph[tid] = (ph4[tid * 4] + ph4[tid * 4 + 1]) + (ph4[tid * 4 + 2] + ph4[tid * 4 + 3]);
    __syncthreads();

    float m[4], l[4], acc[4][4];
#pragma unroll
    for (int i = 0; i < 4; i++) {
        m[i] = ph[ty * 4 + i];
        l[i] = w0;
#pragma unroll
        for (int j = 0; j < 4; j++) acc[i][j] = w0 * bvj[j];
    }

    for (int kt = 0; kt < n; kt += 64) {
        const int nk = min(64, n - kt);
        __syncthreads();
        if (gq < nk) {
            const float* kp = g_qkv + (size_t)(b * T_ + s_idx[kt + gq]) * TD3_ + D_ + h * HD_ + gd * 16;
#pragma unroll
            for (int i = 0; i < 16; i++) Ks[(gd * 16 + i) * 64 + gq] = kp[i];
        } else {
#pragma unroll
            for (int i = 0; i < 16; i++) Ks[(gd * 16 + i) * 64 + gq] = 0.f;
        }
        if (vj < nk) {
            const float* vp = g_qkv + (size_t)(b * T_ + s_idx[kt + vj]) * TD3_ + 2 * D_ + h * HD_ + vdp;
#pragma unroll
            for (int q4 = 0; q4 < 4; q4++)
                *(float4*)&Vs[vj * 68 + vdp + q4 * 4] = ((const float4*)vp)[q4];
        } else {
#pragma unroll
            for (int q4 = 0; q4 < 4; q4++)
                *(float4*)&Vs[vj * 68 + vdp + q4 * 4] = make_float4(0.f, 0.f, 0.f, 0.f);
        }
        __syncthreads();

        float S[4][4];
#pragma unroll
        for (int i = 0; i < 4; i++)
#pragma unroll
            for (int j = 0; j < 4; j++) S[i][j] = 0.f;
#pragma unroll 8
        for (int d = 0; d < 64; d++) {
            float4 aq = *(const float4*)&Qs[d * 64 + ty * 4];
            float4 kk = *(const float4*)&Ks[d * 64 + tx * 4];
            float a[4] = {aq.x, aq.y, aq.z, aq.w};
            float kb[4] = {kk.x, kk.y, kk.z, kk.w};
#pragma unroll
            for (int i = 0; i < 4; i++)
#pragma unroll
                for (int j = 0; j < 4; j++)
                    S[i][j] = fmaf(a[i], kb[j], S[i][j]);
        }

#pragma unroll
        for (int i = 0; i < 4; i++) {
            float mt = -3.0e38f;
#pragma unroll
            for (int j = 0; j < 4; j++)
                if (tx * 4 + j < nk) mt = fmaxf(mt, S[i][j]);
#pragma unroll
            for (int o = 8; o; o >>= 1) mt = fmaxf(mt, __shfl_xor_sync(0xffffffffu, mt, o));
            float mnew = fmaxf(m[i], mt);
            float corr = __expf(m[i] - mnew);
            float ps = 0.f;
#pragma unroll
            for (int j = 0; j < 4; j++) {
                float p = (tx * 4 + j < nk) ? __expf(S[i][j] - mnew) : 0.f;
                S[i][j] = p; ps += p;
            }
#pragma unroll
            for (int o = 8; o; o >>= 1) ps += __shfl_xor_sync(0xffffffffu, ps, o);
            l[i] = l[i] * corr + ps;
            m[i] = mnew;
#pragma unroll
            for (int j = 0; j < 4; j++) acc[i][j] *= corr;
            *(float4*)&Ps[(ty * 4 + i) * 64 + tx * 4] =
                make_float4(S[i][0], S[i][1], S[i][2], S[i][3]);
        }
        __syncthreads();

#pragma unroll 4
        for (int k2 = 0; k2 < 64; k2++) {
            float4 vv = *(const float4*)&Vs[k2 * 68 + tx * 4];
#pragma unroll
            for (int i = 0; i < 4; i++) {
                float p = Ps[(ty * 4 + i) * 64 + k2];
                acc[i][0] = fmaf(p, vv.x, acc[i][0]);
                acc[i][1] = fmaf(p, vv.y, acc[i][1]);
                acc[i][2] = fmaf(p, vv.z, acc[i][2]);
                acc[i][3] = fmaf(p, vv.w, acc[i][3]);
            }
        }
    }

#pragma unroll
    for (int i = 0; i < 4; i++) {
        int qi = qt + ty * 4 + i;
        if (qi < n) {
            float invl = 1.0f / l[i];
            float* op = g_O + (size_t)(b * T_ + s_idx[qi]) * D_ + h * HD_ + tx * 4;
#pragma unroll
            for (int j = 0; j < 4; j++) op[j] = acc[i][j] * invl;
        }
    }
}

// ---------------- launcher ----------------
extern "C" void kernel_launch(void* const* d_in, const int* in_sizes, int n_in,
                              void* d_out, int out_size) {
    const float* X    = (const float*)d_in[0];
    const float* Wc   = (const float*)d_in[1];
    const float* bc   = (const float*)d_in[2];
    const float* Win  = (const float*)d_in[3];
    const float* bin  = (const float*)d_in[4];
    const float* Wout = (const float*)d_in[5];
    const float* bout = (const float*)d_in[6];
    float* out = (float*)d_out;

    void* qkv_p = nullptr; cudaGetSymbolAddress(&qkv_p, g_qkv);
    void* O_p   = nullptr; cudaGetSymbolAddress(&O_p, g_O);

    cudaFuncSetAttribute(attn_kernel, cudaFuncAttributeMaxDynamicSharedMemorySize, ATTN_SMEM);
    cudaFuncSetAttribute(gemm_mma,    cudaFuncAttributeMaxDynamicSharedMemorySize, GEMM_SMEM);

    assign_kernel<<<BT_ / 8, 256>>>(X, Wc, bc);
    build_lists_kernel<<<B_ * C_, 256>>>();
    gemm_mma<<<dim3(TD3_ / 128, BT_ / 128), 256, GEMM_SMEM>>>(X, Win, bin, (float*)qkv_p,
                                                              BT_, TD3_, D_);
    attn_kernel<<<dim3(B_ * C_ * H_, T_ / 64), 256, ATTN_SMEM>>>(bin);
    gemm_mma<<<dim3(D_ / 128, BT_ / 128), 256, GEMM_SMEM>>>((const float*)O_p, Wout, bout, out,
                                                            BT_, D_, D_);
}

// round 5
// speedup vs baseline: 3.8574x; 1.7242x over previous
#include <cuda_runtime.h>
#include <cuda_bf16.h>
#include <cstdint>

#define B_  4
#define T_  1024
#define D_  512
#define C_  8
#define H_  8
#define HD_ 64
#define BT_ (B_*T_)
#define TD3_ (3*D_)

// ---------------- scratch (device globals; no allocation allowed) ----------------
__device__ int   g_assign[BT_];
__device__ int   g_counts[B_*C_];
__device__ int   g_idx[B_*C_*T_];
__device__ float g_qkv[(size_t)BT_*TD3_];   // [b*T+t, 3D]  (q | k | v)
__device__ float g_O[(size_t)BT_*D_];       // attention output

// ---------------- 1) cluster argmax: one warp per token (exact fp32) ----------------
__global__ void assign_kernel(const float* __restrict__ X,
                              const float* __restrict__ Wc,
                              const float* __restrict__ bc) {
    int gw   = (blockIdx.x * blockDim.x + threadIdx.x) >> 5;
    int lane = threadIdx.x & 31;
    if (gw >= BT_) return;
    const float* x = X + (size_t)gw * D_;
    float acc[C_];
#pragma unroll
    for (int c = 0; c < C_; c++) acc[c] = 0.f;
    for (int d = lane; d < D_; d += 32) {
        float xv = x[d];
#pragma unroll
        for (int c = 0; c < C_; c++) acc[c] += xv * Wc[c * D_ + d];
    }
#pragma unroll
    for (int c = 0; c < C_; c++)
#pragma unroll
        for (int o = 16; o; o >>= 1) acc[c] += __shfl_xor_sync(0xffffffffu, acc[c], o);
    if (lane == 0) {
        float best = acc[0] + bc[0];
        int bi = 0;
#pragma unroll
        for (int c = 1; c < C_; c++) {
            float v = acc[c] + bc[c];
            if (v > best) { best = v; bi = c; }
        }
        g_assign[gw] = bi;
    }
}

// ---------------- 2) deterministic per-(b,c) token lists (ballot scan) ----------------
__global__ __launch_bounds__(1024) void build_lists_kernel() {
    int b = blockIdx.x / C_, c = blockIdx.x % C_;
    __shared__ int wtot[32];
    const int tid = threadIdx.x, lane = tid & 31, wid = tid >> 5;
    int p = (g_assign[b * T_ + tid] == c) ? 1 : 0;
    unsigned msk = __ballot_sync(0xffffffffu, p);
    int pre = __popc(msk & ((1u << lane) - 1u));
    if (lane == 0) wtot[wid] = __popc(msk);
    __syncthreads();
    if (wid == 0) {
        int v = wtot[lane], s = v;
#pragma unroll
        for (int o = 1; o < 32; o <<= 1) {
            int u = __shfl_up_sync(0xffffffffu, s, o);
            if (lane >= o) s += u;
        }
        wtot[lane] = s - v;                       // exclusive prefix
        if (lane == 31) g_counts[b * C_ + c] = s; // total
    }
    __syncthreads();
    if (p) g_idx[(b * C_ + c) * T_ + wtot[wid] + pre] = tid;
}

// ---------------- 3/5) 3xBF16 mma.sync NT GEMM ----------------
// C[M,N] = A[M,K]*B[N,K]^T + bias[N]. BM=BN=128, BK=32, 256 thr (8 warps 2Mx4N),
// warp tile 64x32 = 4x4 m16n8k16, 2 k-steps per BK. hi/lo bf16 planes,
// row stride 40 bf16 (20 words) -> conflict-free fragment loads.
#define ROWW   20                    // words per row
#define PLANEW (128 * ROWW)          // words per plane
#define STAGEW (4 * PLANEW)          // Ah | Al | Bh | Bl
#define GEMM_SMEM (2 * STAGEW * 4)   // bytes (81920)

#define MMA_BF16(d, a, b) \
    asm volatile("mma.sync.aligned.m16n8k16.row.col.f32.bf16.bf16.f32 " \
                 "{%0,%1,%2,%3},{%4,%5,%6,%7},{%8,%9},{%0,%1,%2,%3};" \
                 : "+f"((d)[0]), "+f"((d)[1]), "+f"((d)[2]), "+f"((d)[3]) \
                 : "r"((a)[0]), "r"((a)[1]), "r"((a)[2]), "r"((a)[3]), \
                   "r"((b)[0]), "r"((b)[1]))

__device__ __forceinline__ void split2(float x, float y, uint32_t& hi, uint32_t& lo) {
    __nv_bfloat162 h = __floats2bfloat162_rn(x, y);
    float rx = x - __bfloat162float(h.x);
    float ry = y - __bfloat162float(h.y);
    __nv_bfloat162 l = __floats2bfloat162_rn(rx, ry);
    hi = *(uint32_t*)&h;
    lo = *(uint32_t*)&l;
}

__global__ __launch_bounds__(256) void gemm_mma(const float* __restrict__ A,
                                                const float* __restrict__ Bm,
                                                const float* __restrict__ bias,
                                                float* __restrict__ Cm,
                                                int M, int N, int K) {
    extern __shared__ uint32_t smw[];
    const int tid = threadIdx.x, lane = tid & 31, w = tid >> 5;
    const int wm = w & 1, wn = w >> 1;
    const int qr = lane >> 2, qc = lane & 3;
    const int m0 = blockIdx.y * 128, n0 = blockIdx.x * 128;

    // LDG map: row lr (0..127), 16 consecutive k starting at lk
    const int lr = tid >> 1, lk = (tid & 1) * 16;
    const float* Ap = A  + (size_t)(m0 + lr) * K + lk;
    const float* Bp = Bm + (size_t)(n0 + lr) * K + lk;

    float acc[4][4][4];
#pragma unroll
    for (int i = 0; i < 4; i++)
#pragma unroll
        for (int j = 0; j < 4; j++)
#pragma unroll
            for (int e = 0; e < 4; e++) acc[i][j][e] = 0.f;

    float4 ra[4], rb[4];
    auto ldg = [&](int k0) {
#pragma unroll
        for (int i = 0; i < 4; i++) {
            ra[i] = *(const float4*)(Ap + k0 + 4 * i);
            rb[i] = *(const float4*)(Bp + k0 + 4 * i);
        }
    };
    auto sts = [&](int s) {
        uint32_t* Ah = smw + s * STAGEW;
        uint32_t* Al = Ah + PLANEW;
        uint32_t* Bh = Al + PLANEW;
        uint32_t* Bl = Bh + PLANEW;
        const int base = lr * ROWW + (lk >> 1);
        float va[16] = {ra[0].x, ra[0].y, ra[0].z, ra[0].w,
                        ra[1].x, ra[1].y, ra[1].z, ra[1].w,
                        ra[2].x, ra[2].y, ra[2].z, ra[2].w,
                        ra[3].x, ra[3].y, ra[3].z, ra[3].w};
        float vb[16] = {rb[0].x, rb[0].y, rb[0].z, rb[0].w,
                        rb[1].x, rb[1].y, rb[1].z, rb[1].w,
                        rb[2].x, rb[2].y, rb[2].z, rb[2].w,
                        rb[3].x, rb[3].y, rb[3].z, rb[3].w};
#pragma unroll
        for (int e = 0; e < 8; e++) {
            uint32_t h, l;
            split2(va[2 * e], va[2 * e + 1], h, l);
            Ah[base + e] = h; Al[base + e] = l;
            split2(vb[2 * e], vb[2 * e + 1], h, l);
            Bh[base + e] = h; Bl[base + e] = l;
        }
    };
    auto compute = [&](int s) {
        const uint32_t* Ah = smw + s * STAGEW;
        const uint32_t* Al = Ah + PLANEW;
        const uint32_t* Bh = Al + PLANEW;
        const uint32_t* Bl = Bh + PLANEW;
#pragma unroll
        for (int ks = 0; ks < 2; ks++) {
            const int kw = ks * 8 + qc;
            uint32_t ah[4][4], al[4][4], bh[4][2], bl[4][2];
#pragma unroll
            for (int mt = 0; mt < 4; mt++) {
                int r0w = (wm * 64 + mt * 16 + qr) * ROWW + kw;
                int r1w = r0w + 8 * ROWW;
                ah[mt][0] = Ah[r0w];     ah[mt][1] = Ah[r1w];
                ah[mt][2] = Ah[r0w + 4]; ah[mt][3] = Ah[r1w + 4];
                al[mt][0] = Al[r0w];     al[mt][1] = Al[r1w];
                al[mt][2] = Al[r0w + 4]; al[mt][3] = Al[r1w + 4];
            }
#pragma unroll
            for (int nt = 0; nt < 4; nt++) {
                int c0w = (wn * 32 + nt * 8 + qr) * ROWW + kw;
                bh[nt][0] = Bh[c0w]; bh[nt][1] = Bh[c0w + 4];
                bl[nt][0] = Bl[c0w]; bl[nt][1] = Bl[c0w + 4];
            }
#pragma unroll
            for (int mt = 0; mt < 4; mt++)
#pragma unroll
                for (int nt = 0; nt < 4; nt++) {
                    MMA_BF16(acc[mt][nt], ah[mt], bh[nt]);
                    MMA_BF16(acc[mt][nt], ah[mt], bl[nt]);
                    MMA_BF16(acc[mt][nt], al[mt], bh[nt]);
                }
        }
    };

    const int nch = K >> 5;
    ldg(0);
    sts(0);
    __syncthreads();
    for (int ch = 0; ch < nch; ch++) {
        int s = ch & 1;
        if (ch + 1 < nch) ldg((ch + 1) * 32);
        compute(s);
        if (ch + 1 < nch) sts(s ^ 1);
        __syncthreads();
    }

    // epilogue: frag rows qr(+8), cols 2*qc(+1); float2 stores + bias
#pragma unroll
    for (int mt = 0; mt < 4; mt++) {
        int r = m0 + wm * 64 + mt * 16 + qr;
#pragma unroll
        for (int nt = 0; nt < 4; nt++) {
            int cc = n0 + wn * 32 + nt * 8 + 2 * qc;
            float b0 = bias[cc], b1 = bias[cc + 1];
            *(float2*)(Cm + (size_t)r * N + cc) =
                make_float2(acc[mt][nt][0] + b0, acc[mt][nt][1] + b1);
            *(float2*)(Cm + (size_t)(r + 8) * N + cc) =
                make_float2(acc[mt][nt][2] + b0, acc[mt][nt][3] + b1);
        }
    }
}

// ---------------- 4) flash-style clustered attention with phantom key ----------------
// grid = (b*c*h, qtile); block does one 64-query tile over all key tiles.
#define ATTN_SMEM ((1024 + 4096 + 4096 + 64*68 + 4096 + 256 + 64) * 4)

__global__ __launch_bounds__(256) void attn_kernel(const float* __restrict__ bin) {
    extern __shared__ float smf[];
    int*   s_idx = (int*)smf;
    float* Qs  = smf + 1024;
    float* Ks  = Qs + 4096;
    float* Vs  = Ks + 4096;
    float* Ps  = Vs + 64 * 68;
    float* ph4 = Ps + 4096;
    float* ph  = ph4 + 256;

    const int bid = blockIdx.x;
    const int h = bid & 7;
    const int c = (bid >> 3) & 7;
    const int b = bid >> 6;
    const int n = g_counts[b * C_ + c];
    const int qt = blockIdx.y * 64;
    if (qt >= n) return;
    const int* idx = g_idx + (b * C_ + c) * T_;
    const int tid = threadIdx.x;
    for (int i = tid; i < n; i += 256) s_idx[i] = idx[i];
    __syncthreads();

    const float w0 = (float)(T_ - n);
    const float* bk = bin + D_     + h * HD_;
    const float* bv = bin + 2 * D_ + h * HD_;
    const int tx = tid & 15, ty = tid >> 4;
    const int gq = tid & 63, gd = tid >> 6;
    const int vj = tid >> 2, vdp = (tid & 3) * 16;

    float bvj[4];
#pragma unroll
    for (int j = 0; j < 4; j++) bvj[j] = bv[tx * 4 + j];

    const int nq = min(64, n - qt);
    {
        float p = 0.f;
        if (gq < nq) {
            const float* qp = g_qkv + (size_t)(b * T_ + s_idx[qt + gq]) * TD3_ + h * HD_ + gd * 16;
#pragma unroll
            for (int i = 0; i < 16; i++) {
                float v = qp[i] * 0.125f;
                Qs[(gd * 16 + i) * 64 + gq] = v;
                p = fmaf(v, bk[gd * 16 + i], p);
            }
        } else {
#pragma unroll
            for (int i = 0; i < 16; i++) Qs[(gd * 16 + i) * 64 + gq] = 0.f;
        }
        ph4[gq * 4 + gd] = p;
    }
    __syncthreads();
    if (tid < 64)
        ph[tid] = (ph4[tid * 4] + ph4[tid * 4 + 1]) + (ph4[tid * 4 + 2] + ph4[tid * 4 + 3]);
    __syncthreads();

    float m[4], l[4], acc[4][4];
#pragma unroll
    for (int i = 0; i < 4; i++) {
        m[i] = ph[ty * 4 + i];
        l[i] = w0;
#pragma unroll
        for (int j = 0; j < 4; j++) acc[i][j] = w0 * bvj[j];
    }

    for (int kt = 0; kt < n; kt += 64) {
        const int nk = min(64, n - kt);
        __syncthreads();
        if (gq < nk) {
            const float* kp = g_qkv + (size_t)(b * T_ + s_idx[kt + gq]) * TD3_ + D_ + h * HD_ + gd * 16;
#pragma unroll
            for (int i = 0; i < 16; i++) Ks[(gd * 16 + i) * 64 + gq] = kp[i];
        } else {
#pragma unroll
            for (int i = 0; i < 16; i++) Ks[(gd * 16 + i) * 64 + gq] = 0.f;
        }
        if (vj < nk) {
            const float* vp = g_qkv + (size_t)(b * T_ + s_idx[kt + vj]) * TD3_ + 2 * D_ + h * HD_ + vdp;
#pragma unroll
            for (int q4 = 0; q4 < 4; q4++)
                *(float4*)&Vs[vj * 68 + vdp + q4 * 4] = ((const float4*)vp)[q4];
        } else {
#pragma unroll
            for (int q4 = 0; q4 < 4; q4++)
                *(float4*)&Vs[vj * 68 + vdp + q4 * 4] = make_float4(0.f, 0.f, 0.f, 0.f);
        }
        __syncthreads();

        float S[4][4];
#pragma unroll
        for (int i = 0; i < 4; i++)
#pragma unroll
            for (int j = 0; j < 4; j++) S[i][j] = 0.f;
#pragma unroll 8
        for (int d = 0; d < 64; d++) {
            float4 aq = *(const float4*)&Qs[d * 64 + ty * 4];
            float4 kk = *(const float4*)&Ks[d * 64 + tx * 4];
            float a[4] = {aq.x, aq.y, aq.z, aq.w};
            float kb[4] = {kk.x, kk.y, kk.z, kk.w};
#pragma unroll
            for (int i = 0; i < 4; i++)
#pragma unroll
                for (int j = 0; j < 4; j++)
                    S[i][j] = fmaf(a[i], kb[j], S[i][j]);
        }

#pragma unroll
        for (int i = 0; i < 4; i++) {
            float mt = -3.0e38f;
#pragma unroll
            for (int j = 0; j < 4; j++)
                if (tx * 4 + j < nk) mt = fmaxf(mt, S[i][j]);
#pragma unroll
            for (int o = 8; o; o >>= 1) mt = fmaxf(mt, __shfl_xor_sync(0xffffffffu, mt, o));
            float mnew = fmaxf(m[i], mt);
            float corr = __expf(m[i] - mnew);
            float ps = 0.f;
#pragma unroll
            for (int j = 0; j < 4; j++) {
                float p = (tx * 4 + j < nk) ? __expf(S[i][j] - mnew) : 0.f;
                S[i][j] = p; ps += p;
            }
#pragma unroll
            for (int o = 8; o; o >>= 1) ps += __shfl_xor_sync(0xffffffffu, ps, o);
            l[i] = l[i] * corr + ps;
            m[i] = mnew;
#pragma unroll
            for (int j = 0; j < 4; j++) acc[i][j] *= corr;
            *(float4*)&Ps[(ty * 4 + i) * 64 + tx * 4] =
                make_float4(S[i][0], S[i][1], S[i][2], S[i][3]);
        }
        __syncthreads();

#pragma unroll 4
        for (int k2 = 0; k2 < 64; k2++) {
            float4 vv = *(const float4*)&Vs[k2 * 68 + tx * 4];
#pragma unroll
            for (int i = 0; i < 4; i++) {
                float p = Ps[(ty * 4 + i) * 64 + k2];
                acc[i][0] = fmaf(p, vv.x, acc[i][0]);
                acc[i][1] = fmaf(p, vv.y, acc[i][1]);
                acc[i][2] = fmaf(p, vv.z, acc[i][2]);
                acc[i][3] = fmaf(p, vv.w, acc[i][3]);
            }
        }
    }

#pragma unroll
    for (int i = 0; i < 4; i++) {
        int qi = qt + ty * 4 + i;
        if (qi < n) {
            float invl = 1.0f / l[i];
            float* op = g_O + (size_t)(b * T_ + s_idx[qi]) * D_ + h * HD_ + tx * 4;
#pragma unroll
            for (int j = 0; j < 4; j++) op[j] = acc[i][j] * invl;
        }
    }
}

// ---------------- launcher ----------------
extern "C" void kernel_launch(void* const* d_in, const int* in_sizes, int n_in,
                              void* d_out, int out_size) {
    const float* X    = (const float*)d_in[0];
    const float* Wc   = (const float*)d_in[1];
    const float* bc   = (const float*)d_in[2];
    const float* Win  = (const float*)d_in[3];
    const float* bin  = (const float*)d_in[4];
    const float* Wout = (const float*)d_in[5];
    const float* bout = (const float*)d_in[6];
    float* out = (float*)d_out;

    void* qkv_p = nullptr; cudaGetSymbolAddress(&qkv_p, g_qkv);
    void* O_p   = nullptr; cudaGetSymbolAddress(&O_p, g_O);

    cudaFuncSetAttribute(attn_kernel, cudaFuncAttributeMaxDynamicSharedMemorySize, ATTN_SMEM);
    cudaFuncSetAttribute(gemm_mma,    cudaFuncAttributeMaxDynamicSharedMemorySize, GEMM_SMEM);

    assign_kernel<<<BT_ / 8, 256>>>(X, Wc, bc);
    build_lists_kernel<<<B_ * C_, 1024>>>();
    gemm_mma<<<dim3(TD3_ / 128, BT_ / 128), 256, GEMM_SMEM>>>(X, Win, bin, (float*)qkv_p,
                                                              BT_, TD3_, D_);
    attn_kernel<<<dim3(B_ * C_ * H_, T_ / 64), 256, ATTN_SMEM>>>(bin);
    gemm_mma<<<dim3(D_ / 128, BT_ / 128), 256, GEMM_SMEM>>>((const float*)O_p, Wout, bout, out,
                                                            BT_, D_, D_);
}

// round 6
// speedup vs baseline: 5.1693x; 1.3401x over previous
#include <cuda_runtime.h>
#include <cuda_bf16.h>
#include <cstdint>

#define B_  4
#define T_  1024
#define D_  512
#define C_  8
#define H_  8
#define HD_ 64
#define BT_ (B_*T_)
#define TD3_ (3*D_)

// ---------------- scratch (device globals; no allocation allowed) ----------------
__device__ int   g_assign[BT_];
__device__ int   g_counts[B_*C_];
__device__ int   g_idx[B_*C_*T_];
__device__ float g_qkv[(size_t)BT_*TD3_];   // [b*T+t, 3D]  (q | k | v)
__device__ float g_O[(size_t)BT_*D_];       // attention output

#define MMA_BF16(d, a, b) \
    asm volatile("mma.sync.aligned.m16n8k16.row.col.f32.bf16.bf16.f32 " \
                 "{%0,%1,%2,%3},{%4,%5,%6,%7},{%8,%9},{%0,%1,%2,%3};" \
                 : "+f"((d)[0]), "+f"((d)[1]), "+f"((d)[2]), "+f"((d)[3]) \
                 : "r"((a)[0]), "r"((a)[1]), "r"((a)[2]), "r"((a)[3]), \
                   "r"((b)[0]), "r"((b)[1]))

__device__ __forceinline__ void split2(float x, float y, uint32_t& hi, uint32_t& lo) {
    __nv_bfloat162 h = __floats2bfloat162_rn(x, y);
    float rx = x - __bfloat162float(h.x);
    float ry = y - __bfloat162float(h.y);
    __nv_bfloat162 l = __floats2bfloat162_rn(rx, ry);
    hi = *(uint32_t*)&h;
    lo = *(uint32_t*)&l;
}

// ---------------- 1) cluster argmax: one warp per token (exact fp32) ----------------
__global__ void assign_kernel(const float* __restrict__ X,
                              const float* __restrict__ Wc,
                              const float* __restrict__ bc) {
    int gw   = (blockIdx.x * blockDim.x + threadIdx.x) >> 5;
    int lane = threadIdx.x & 31;
    if (gw >= BT_) return;
    const float* x = X + (size_t)gw * D_;
    float acc[C_];
#pragma unroll
    for (int c = 0; c < C_; c++) acc[c] = 0.f;
    for (int d = lane; d < D_; d += 32) {
        float xv = x[d];
#pragma unroll
        for (int c = 0; c < C_; c++) acc[c] += xv * Wc[c * D_ + d];
    }
#pragma unroll
    for (int c = 0; c < C_; c++)
#pragma unroll
        for (int o = 16; o; o >>= 1) acc[c] += __shfl_xor_sync(0xffffffffu, acc[c], o);
    if (lane == 0) {
        float best = acc[0] + bc[0];
        int bi = 0;
#pragma unroll
        for (int c = 1; c < C_; c++) {
            float v = acc[c] + bc[c];
            if (v > best) { best = v; bi = c; }
        }
        g_assign[gw] = bi;
    }
}

// ---------------- 2) deterministic per-(b,c) token lists (ballot scan) ----------------
__global__ __launch_bounds__(1024) void build_lists_kernel() {
    int b = blockIdx.x / C_, c = blockIdx.x % C_;
    __shared__ int wtot[32];
    const int tid = threadIdx.x, lane = tid & 31, wid = tid >> 5;
    int p = (g_assign[b * T_ + tid] == c) ? 1 : 0;
    unsigned msk = __ballot_sync(0xffffffffu, p);
    int pre = __popc(msk & ((1u << lane) - 1u));
    if (lane == 0) wtot[wid] = __popc(msk);
    __syncthreads();
    if (wid == 0) {
        int v = wtot[lane], s = v;
#pragma unroll
        for (int o = 1; o < 32; o <<= 1) {
            int u = __shfl_up_sync(0xffffffffu, s, o);
            if (lane >= o) s += u;
        }
        wtot[lane] = s - v;
        if (lane == 31) g_counts[b * C_ + c] = s;
    }
    __syncthreads();
    if (p) g_idx[(b * C_ + c) * T_ + wtot[wid] + pre] = tid;
}

// ---------------- 3/5) 3xBF16 mma.sync NT GEMM (unchanged from R5) ----------------
#define ROWW   20
#define PLANEW (128 * ROWW)
#define STAGEW (4 * PLANEW)
#define GEMM_SMEM (2 * STAGEW * 4)

__global__ __launch_bounds__(256) void gemm_mma(const float* __restrict__ A,
                                                const float* __restrict__ Bm,
                                                const float* __restrict__ bias,
                                                float* __restrict__ Cm,
                                                int M, int N, int K) {
    extern __shared__ uint32_t smw[];
    const int tid = threadIdx.x, lane = tid & 31, w = tid >> 5;
    const int wm = w & 1, wn = w >> 1;
    const int qr = lane >> 2, qc = lane & 3;
    const int m0 = blockIdx.y * 128, n0 = blockIdx.x * 128;

    const int lr = tid >> 1, lk = (tid & 1) * 16;
    const float* Ap = A  + (size_t)(m0 + lr) * K + lk;
    const float* Bp = Bm + (size_t)(n0 + lr) * K + lk;

    float acc[4][4][4];
#pragma unroll
    for (int i = 0; i < 4; i++)
#pragma unroll
        for (int j = 0; j < 4; j++)
#pragma unroll
            for (int e = 0; e < 4; e++) acc[i][j][e] = 0.f;

    float4 ra[4], rb[4];
    auto ldg = [&](int k0) {
#pragma unroll
        for (int i = 0; i < 4; i++) {
            ra[i] = *(const float4*)(Ap + k0 + 4 * i);
            rb[i] = *(const float4*)(Bp + k0 + 4 * i);
        }
    };
    auto sts = [&](int s) {
        uint32_t* Ah = smw + s * STAGEW;
        uint32_t* Al = Ah + PLANEW;
        uint32_t* Bh = Al + PLANEW;
        uint32_t* Bl = Bh + PLANEW;
        const int base = lr * ROWW + (lk >> 1);
        float va[16] = {ra[0].x, ra[0].y, ra[0].z, ra[0].w,
                        ra[1].x, ra[1].y, ra[1].z, ra[1].w,
                        ra[2].x, ra[2].y, ra[2].z, ra[2].w,
                        ra[3].x, ra[3].y, ra[3].z, ra[3].w};
        float vb[16] = {rb[0].x, rb[0].y, rb[0].z, rb[0].w,
                        rb[1].x, rb[1].y, rb[1].z, rb[1].w,
                        rb[2].x, rb[2].y, rb[2].z, rb[2].w,
                        rb[3].x, rb[3].y, rb[3].z, rb[3].w};
#pragma unroll
        for (int e = 0; e < 8; e++) {
            uint32_t h, l;
            split2(va[2 * e], va[2 * e + 1], h, l);
            Ah[base + e] = h; Al[base + e] = l;
            split2(vb[2 * e], vb[2 * e + 1], h, l);
            Bh[base + e] = h; Bl[base + e] = l;
        }
    };
    auto compute = [&](int s) {
        const uint32_t* Ah = smw + s * STAGEW;
        const uint32_t* Al = Ah + PLANEW;
        const uint32_t* Bh = Al + PLANEW;
        const uint32_t* Bl = Bh + PLANEW;
#pragma unroll
        for (int ks = 0; ks < 2; ks++) {
            const int kw = ks * 8 + qc;
            uint32_t ah[4][4], al[4][4], bh[4][2], bl[4][2];
#pragma unroll
            for (int mt = 0; mt < 4; mt++) {
                int r0w = (wm * 64 + mt * 16 + qr) * ROWW + kw;
                int r1w = r0w + 8 * ROWW;
                ah[mt][0] = Ah[r0w];     ah[mt][1] = Ah[r1w];
                ah[mt][2] = Ah[r0w + 4]; ah[mt][3] = Ah[r1w + 4];
                al[mt][0] = Al[r0w];     al[mt][1] = Al[r1w];
                al[mt][2] = Al[r0w + 4]; al[mt][3] = Al[r1w + 4];
            }
#pragma unroll
            for (int nt = 0; nt < 4; nt++) {
                int c0w = (wn * 32 + nt * 8 + qr) * ROWW + kw;
                bh[nt][0] = Bh[c0w]; bh[nt][1] = Bh[c0w + 4];
                bl[nt][0] = Bl[c0w]; bl[nt][1] = Bl[c0w + 4];
            }
#pragma unroll
            for (int mt = 0; mt < 4; mt++)
#pragma unroll
                for (int nt = 0; nt < 4; nt++) {
                    MMA_BF16(acc[mt][nt], ah[mt], bh[nt]);
                    MMA_BF16(acc[mt][nt], ah[mt], bl[nt]);
                    MMA_BF16(acc[mt][nt], al[mt], bh[nt]);
                }
        }
    };

    const int nch = K >> 5;
    ldg(0);
    sts(0);
    __syncthreads();
    for (int ch = 0; ch < nch; ch++) {
        int s = ch & 1;
        if (ch + 1 < nch) ldg((ch + 1) * 32);
        compute(s);
        if (ch + 1 < nch) sts(s ^ 1);
        __syncthreads();
    }

#pragma unroll
    for (int mt = 0; mt < 4; mt++) {
        int r = m0 + wm * 64 + mt * 16 + qr;
#pragma unroll
        for (int nt = 0; nt < 4; nt++) {
            int cc = n0 + wn * 32 + nt * 8 + 2 * qc;
            float b0 = bias[cc], b1 = bias[cc + 1];
            *(float2*)(Cm + (size_t)r * N + cc) =
                make_float2(acc[mt][nt][0] + b0, acc[mt][nt][1] + b1);
            *(float2*)(Cm + (size_t)(r + 8) * N + cc) =
                make_float2(acc[mt][nt][2] + b0, acc[mt][nt][3] + b1);
        }
    }
}

// ---------------- 4) 3xBF16 mma flash attention with phantom key ----------------
// grid = (b*c*h, qtile/128); 8 warps, warp = 16 q-rows x 64 keys per ktile.
// SMEM words: s_idx 1024 | ph 128 | Qh 128*36 | Ql | Kh 64*36 | Kl | Vh | Vl
#define AST 36                         // row stride in words (conflict-free frags)
#define ATTN_SMEM ((1024 + 128 + 2*128*AST + 4*64*AST) * 4)

__global__ __launch_bounds__(256) void attn_kernel(const float* __restrict__ bin) {
    extern __shared__ uint32_t smu[];
    int*      s_idx = (int*)smu;               // 1024
    float*    ph    = (float*)(smu + 1024);    // 128
    uint32_t* Qh = smu + 1024 + 128;
    uint32_t* Ql = Qh + 128 * AST;
    uint32_t* Kh = Ql + 128 * AST;
    uint32_t* Kl = Kh + 64 * AST;
    uint32_t* Vh = Kl + 64 * AST;
    uint32_t* Vl = Vh + 64 * AST;

    const int bid = blockIdx.x;
    const int h = bid & 7;
    const int c = (bid >> 3) & 7;
    const int b = bid >> 6;
    const int n = g_counts[b * C_ + c];
    const int qt = blockIdx.y * 128;
    if (qt >= n) return;
    const int* idx = g_idx + (b * C_ + c) * T_;
    const int tid = threadIdx.x;
    for (int i = tid; i < n; i += 256) s_idx[i] = idx[i];
    __syncthreads();

    const float w0 = (float)(T_ - n);
    const float* bk = bin + D_     + h * HD_;
    const float* bv = bin + 2 * D_ + h * HD_;
    const int w = tid >> 5, lane = tid & 31;
    const int qr = lane >> 2, qc = lane & 3;

    // ---- gather Q (scaled 0.125) into bf16 hi/lo planes + phantom partials ----
    {
        const int r = tid >> 1, hf = (tid & 1) * 32;
        const int wb = r * AST + hf / 2;
        float pacc = 0.f;
        int qi = qt + r;
        if (qi < n) {
            const float* qp = g_qkv + (size_t)(b * T_ + s_idx[qi]) * TD3_ + h * HD_ + hf;
#pragma unroll
            for (int j4 = 0; j4 < 8; j4++) {
                float4 v = ((const float4*)qp)[j4];
                v.x *= 0.125f; v.y *= 0.125f; v.z *= 0.125f; v.w *= 0.125f;
                uint32_t hh, ll;
                split2(v.x, v.y, hh, ll);
                Qh[wb + 2 * j4] = hh; Ql[wb + 2 * j4] = ll;
                split2(v.z, v.w, hh, ll);
                Qh[wb + 2 * j4 + 1] = hh; Ql[wb + 2 * j4 + 1] = ll;
                int d = hf + 4 * j4;
                pacc = fmaf(v.x, bk[d], pacc);
                pacc = fmaf(v.y, bk[d + 1], pacc);
                pacc = fmaf(v.z, bk[d + 2], pacc);
                pacc = fmaf(v.w, bk[d + 3], pacc);
            }
        } else {
#pragma unroll
            for (int j = 0; j < 16; j++) { Qh[wb + j] = 0u; Ql[wb + j] = 0u; }
        }
        pacc += __shfl_xor_sync(0xffffffffu, pacc, 1);
        if ((tid & 1) == 0) ph[r] = pacc;
    }
    __syncthreads();

    // ---- resident Q fragments ----
    uint32_t qfh[16], qfl[16];
#pragma unroll
    for (int ks = 0; ks < 4; ks++) {
        int a0 = (w * 16 + qr) * AST + ks * 8 + qc;
        int a1 = a0 + 8 * AST;
        qfh[ks * 4 + 0] = Qh[a0];     qfh[ks * 4 + 1] = Qh[a1];
        qfh[ks * 4 + 2] = Qh[a0 + 4]; qfh[ks * 4 + 3] = Qh[a1 + 4];
        qfl[ks * 4 + 0] = Ql[a0];     qfl[ks * 4 + 1] = Ql[a1];
        qfl[ks * 4 + 2] = Ql[a0 + 4]; qfl[ks * 4 + 3] = Ql[a1 + 4];
    }

    // ---- init online-softmax state (phantom key of multiplicity w0) ----
    float m0 = ph[w * 16 + qr], m1 = ph[w * 16 + qr + 8];
    float l0 = w0, l1 = w0;
    float O[8][4];
#pragma unroll
    for (int dnt = 0; dnt < 8; dnt++) {
        int col = dnt * 8 + 2 * qc;
        O[dnt][0] = w0 * bv[col];
        O[dnt][1] = w0 * bv[col + 1];
        O[dnt][2] = O[dnt][0];
        O[dnt][3] = O[dnt][1];
    }

    // ---- key-tile loop ----
    for (int kt = 0; kt < n; kt += 64) {
        const int nk = min(64, n - kt);
        __syncthreads();
        // gather K [key][d] hi/lo
        {
            const int tk = tid >> 2, dq = (tid & 3) * 16;
            const int wb = tk * AST + dq / 2;
            if (kt + tk < n) {
                const float* kp = g_qkv + (size_t)(b * T_ + s_idx[kt + tk]) * TD3_ + D_ + h * HD_ + dq;
#pragma unroll
                for (int j4 = 0; j4 < 4; j4++) {
                    float4 v = ((const float4*)kp)[j4];
                    uint32_t hh, ll;
                    split2(v.x, v.y, hh, ll);
                    Kh[wb + 2 * j4] = hh; Kl[wb + 2 * j4] = ll;
                    split2(v.z, v.w, hh, ll);
                    Kh[wb + 2 * j4 + 1] = hh; Kl[wb + 2 * j4 + 1] = ll;
                }
            } else {
#pragma unroll
                for (int j = 0; j < 8; j++) { Kh[wb + j] = 0u; Kl[wb + j] = 0u; }
            }
            // gather V transposed [d][key] hi/lo (2-byte scatter stores)
            __nv_bfloat16* VhB = (__nv_bfloat16*)Vh;
            __nv_bfloat16* VlB = (__nv_bfloat16*)Vl;
            if (kt + tk < n) {
                const float* vp = g_qkv + (size_t)(b * T_ + s_idx[kt + tk]) * TD3_ + 2 * D_ + h * HD_ + dq;
#pragma unroll
                for (int j4 = 0; j4 < 4; j4++) {
                    float4 v = ((const float4*)vp)[j4];
                    float vv[4] = {v.x, v.y, v.z, v.w};
#pragma unroll
                    for (int e = 0; e < 4; e++) {
                        int d = dq + 4 * j4 + e;
                        __nv_bfloat16 hh = __float2bfloat16(vv[e]);
                        VhB[d * (2 * AST) + tk] = hh;
                        VlB[d * (2 * AST) + tk] = __float2bfloat16(vv[e] - __bfloat162float(hh));
                    }
                }
            } else {
#pragma unroll
                for (int e = 0; e < 16; e++) {
                    int d = dq + e;
                    VhB[d * (2 * AST) + tk] = __float2bfloat16(0.f);
                    VlB[d * (2 * AST) + tk] = __float2bfloat16(0.f);
                }
            }
        }
        __syncthreads();

        // S = Q K^T via 3xBF16 mma; per warp 16x64
        float S[8][4];
#pragma unroll
        for (int nt = 0; nt < 8; nt++) {
            S[nt][0] = S[nt][1] = S[nt][2] = S[nt][3] = 0.f;
            int kb = (nt * 8 + qr) * AST + qc;
#pragma unroll
            for (int ks = 0; ks < 4; ks++) {
                uint32_t bh[2] = {Kh[kb + ks * 8], Kh[kb + ks * 8 + 4]};
                uint32_t bl[2] = {Kl[kb + ks * 8], Kl[kb + ks * 8 + 4]};
                MMA_BF16(S[nt], qfh + ks * 4, bh);
                MMA_BF16(S[nt], qfh + ks * 4, bl);
                MMA_BF16(S[nt], qfl + ks * 4, bh);
            }
        }

        // mask padded key columns
        if (nk < 64) {
#pragma unroll
            for (int nt = 0; nt < 8; nt++) {
                int c0 = nt * 8 + 2 * qc;
                if (c0 >= nk)     { S[nt][0] = -1e30f; S[nt][2] = -1e30f; }
                if (c0 + 1 >= nk) { S[nt][1] = -1e30f; S[nt][3] = -1e30f; }
            }
        }

        // online softmax (rows qr, qr+8)
        float r0 = -1e30f, r1 = -1e30f;
#pragma unroll
        for (int nt = 0; nt < 8; nt++) {
            r0 = fmaxf(r0, fmaxf(S[nt][0], S[nt][1]));
            r1 = fmaxf(r1, fmaxf(S[nt][2], S[nt][3]));
        }
        r0 = fmaxf(r0, __shfl_xor_sync(0xffffffffu, r0, 1));
        r0 = fmaxf(r0, __shfl_xor_sync(0xffffffffu, r0, 2));
        r1 = fmaxf(r1, __shfl_xor_sync(0xffffffffu, r1, 1));
        r1 = fmaxf(r1, __shfl_xor_sync(0xffffffffu, r1, 2));
        float mn0 = fmaxf(m0, r0), mn1 = fmaxf(m1, r1);
        float co0 = __expf(m0 - mn0), co1 = __expf(m1 - mn1);
        float s0 = 0.f, s1 = 0.f;
#pragma unroll
        for (int nt = 0; nt < 8; nt++) {
            S[nt][0] = __expf(S[nt][0] - mn0);
            S[nt][1] = __expf(S[nt][1] - mn0);
            S[nt][2] = __expf(S[nt][2] - mn1);
            S[nt][3] = __expf(S[nt][3] - mn1);
            s0 += S[nt][0] + S[nt][1];
            s1 += S[nt][2] + S[nt][3];
        }
        s0 += __shfl_xor_sync(0xffffffffu, s0, 1);
        s0 += __shfl_xor_sync(0xffffffffu, s0, 2);
        s1 += __shfl_xor_sync(0xffffffffu, s1, 1);
        s1 += __shfl_xor_sync(0xffffffffu, s1, 2);
        l0 = l0 * co0 + s0;
        l1 = l1 * co1 + s1;
        m0 = mn0; m1 = mn1;
#pragma unroll
        for (int dnt = 0; dnt < 8; dnt++) {
            O[dnt][0] *= co0; O[dnt][1] *= co0;
            O[dnt][2] *= co1; O[dnt][3] *= co1;
        }

        // pack P into a-fragments (hi/lo) — pure register shuffle-free remap
        uint32_t pfh[16], pfl[16];
#pragma unroll
        for (int u = 0; u < 4; u++) {
            split2(S[2 * u][0],     S[2 * u][1],     pfh[u * 4 + 0], pfl[u * 4 + 0]);
            split2(S[2 * u][2],     S[2 * u][3],     pfh[u * 4 + 1], pfl[u * 4 + 1]);
            split2(S[2 * u + 1][0], S[2 * u + 1][1], pfh[u * 4 + 2], pfl[u * 4 + 2]);
            split2(S[2 * u + 1][2], S[2 * u + 1][3], pfh[u * 4 + 3], pfl[u * 4 + 3]);
        }

        // O += P V via 3xBF16 mma
#pragma unroll
        for (int dnt = 0; dnt < 8; dnt++) {
            int vb = (dnt * 8 + qr) * AST + qc;
#pragma unroll
            for (int u = 0; u < 4; u++) {
                uint32_t vh[2] = {Vh[vb + u * 8], Vh[vb + u * 8 + 4]};
                uint32_t vl[2] = {Vl[vb + u * 8], Vl[vb + u * 8 + 4]};
                MMA_BF16(O[dnt], pfh + u * 4, vh);
                MMA_BF16(O[dnt], pfl + u * 4, vh);
                MMA_BF16(O[dnt], pfh + u * 4, vl);
            }
        }
    }

    // ---- normalize + scatter store ----
    float i0 = 1.0f / l0, i1 = 1.0f / l1;
    int row0 = qt + w * 16 + qr;
    if (row0 < n) {
        float* op = g_O + (size_t)(b * T_ + s_idx[row0]) * D_ + h * HD_;
#pragma unroll
        for (int dnt = 0; dnt < 8; dnt++)
            *(float2*)(op + dnt * 8 + 2 * qc) =
                make_float2(O[dnt][0] * i0, O[dnt][1] * i0);
    }
    int row1 = row0 + 8;
    if (row1 < n) {
        float* op = g_O + (size_t)(b * T_ + s_idx[row1]) * D_ + h * HD_;
#pragma unroll
        for (int dnt = 0; dnt < 8; dnt++)
            *(float2*)(op + dnt * 8 + 2 * qc) =
                make_float2(O[dnt][2] * i1, O[dnt][3] * i1);
    }
}

// ---------------- launcher ----------------
extern "C" void kernel_launch(void* const* d_in, const int* in_sizes, int n_in,
                              void* d_out, int out_size) {
    const float* X    = (const float*)d_in[0];
    const float* Wc   = (const float*)d_in[1];
    const float* bc   = (const float*)d_in[2];
    const float* Win  = (const float*)d_in[3];
    const float* bin  = (const float*)d_in[4];
    const float* Wout = (const float*)d_in[5];
    const float* bout = (const float*)d_in[6];
    float* out = (float*)d_out;

    void* qkv_p = nullptr; cudaGetSymbolAddress(&qkv_p, g_qkv);
    void* O_p   = nullptr; cudaGetSymbolAddress(&O_p, g_O);

    cudaFuncSetAttribute(attn_kernel, cudaFuncAttributeMaxDynamicSharedMemorySize, ATTN_SMEM);
    cudaFuncSetAttribute(gemm_mma,    cudaFuncAttributeMaxDynamicSharedMemorySize, GEMM_SMEM);

    assign_kernel<<<BT_ / 8, 256>>>(X, Wc, bc);
    build_lists_kernel<<<B_ * C_, 1024>>>();
    gemm_mma<<<dim3(TD3_ / 128, BT_ / 128), 256, GEMM_SMEM>>>(X, Win, bin, (float*)qkv_p,
                                                              BT_, TD3_, D_);
    attn_kernel<<<dim3(B_ * C_ * H_, T_ / 128), 256, ATTN_SMEM>>>(bin);
    gemm_mma<<<dim3(D_ / 128, BT_ / 128), 256, GEMM_SMEM>>>((const float*)O_p, Wout, bout, out,
                                                            BT_, D_, D_);
}